// round 3
// baseline (speedup 1.0000x reference)
#include <cuda_runtime.h>
#include <cuda_bf16.h>
#include <cstdint>

// MeanAggregator: out[i,:] = mean_{e<EPN} features[edge_dst[i*EPN+e], :], D=128 f32.
// One warp per node; lane l owns float4 columns [4l,4l+4).
//
// R3: ptxas collapsed the C++ "load-all-then-reduce" structure twice (regs 32/38).
// Force MLP=EPN with asm volatile ld.global.nc.v4.f32 — volatile asm statements
// cannot be reordered w.r.t. each other, so all 17 gathers are in flight before
// the first FADD. Indices: 1 coalesced LDG.32 + SHFL broadcasts (saves 16
// broadcast-LDG wavefronts per warp).

#define D_DIM 128

template <int EPN>
__global__ __launch_bounds__(256) void mean_agg_kernel_fixed(
    const float* __restrict__ feat,
    const int*   __restrict__ edge_dst,
    float*       __restrict__ out,
    int B)
{
    const int warp = (blockIdx.x * blockDim.x + threadIdx.x) >> 5;
    const int lane = threadIdx.x & 31;
    if (warp >= B) return;

    static_assert(EPN <= 32, "index-shuffle trick needs EPN <= 32");

    // One coalesced index load per warp; broadcast via shuffle.
    const int* __restrict__ idx = edge_dst + (size_t)warp * EPN;
    int myidx = 0;
    if (lane < EPN) myidx = __ldg(idx + lane);

    // All EPN gathers issued back-to-back (asm volatile pins ordering).
    float4 v[EPN];
#pragma unroll
    for (int e = 0; e < EPN; ++e) {
        const int nb = __shfl_sync(0xFFFFFFFFu, myidx, e);
        const float* p = feat + (size_t)nb * D_DIM + lane * 4;
        asm volatile("ld.global.nc.v4.f32 {%0,%1,%2,%3}, [%4];"
                     : "=f"(v[e].x), "=f"(v[e].y), "=f"(v[e].z), "=f"(v[e].w)
                     : "l"(p));
    }

    // Pairwise-tree reduction (short FADD chains).
#pragma unroll
    for (int stride = 1; stride < EPN; stride <<= 1) {
#pragma unroll
        for (int e = 0; e + stride < EPN; e += 2 * stride) {
            v[e].x += v[e + stride].x;
            v[e].y += v[e + stride].y;
            v[e].z += v[e + stride].z;
            v[e].w += v[e + stride].w;
        }
    }

    const float inv = 1.0f / (float)EPN;
    float4 r;
    r.x = v[0].x * inv; r.y = v[0].y * inv;
    r.z = v[0].z * inv; r.w = v[0].w * inv;

    reinterpret_cast<float4*>(out + (size_t)warp * D_DIM)[lane] = r;
}

// General fallback: runtime EPN, batches of 8 forced-in-flight gathers.
__global__ __launch_bounds__(256) void mean_agg_kernel_dyn(
    const float* __restrict__ feat,
    const int*   __restrict__ edge_dst,
    float*       __restrict__ out,
    int B, int epn)
{
    const int warp = (blockIdx.x * blockDim.x + threadIdx.x) >> 5;
    const int lane = threadIdx.x & 31;
    if (warp >= B) return;

    const int* __restrict__ idx = edge_dst + (size_t)warp * epn;

    float4 acc = make_float4(0.f, 0.f, 0.f, 0.f);
    int e = 0;
    for (; e + 8 <= epn; e += 8) {
        float4 v[8];
#pragma unroll
        for (int j = 0; j < 8; ++j) {
            const int nb = __ldg(idx + e + j);
            const float* p = feat + (size_t)nb * D_DIM + lane * 4;
            asm volatile("ld.global.nc.v4.f32 {%0,%1,%2,%3}, [%4];"
                         : "=f"(v[j].x), "=f"(v[j].y), "=f"(v[j].z), "=f"(v[j].w)
                         : "l"(p));
        }
#pragma unroll
        for (int j = 0; j < 8; ++j) {
            acc.x += v[j].x; acc.y += v[j].y;
            acc.z += v[j].z; acc.w += v[j].w;
        }
    }
    for (; e < epn; ++e) {
        const int nb = __ldg(idx + e);
        const float4 t = __ldg(reinterpret_cast<const float4*>(
                                   feat + (size_t)nb * D_DIM) + lane);
        acc.x += t.x; acc.y += t.y; acc.z += t.z; acc.w += t.w;
    }

    const float inv = 1.0f / (float)epn;
    acc.x *= inv; acc.y *= inv; acc.z *= inv; acc.w *= inv;
    reinterpret_cast<float4*>(out + (size_t)warp * D_DIM)[lane] = acc;
}

extern "C" void kernel_launch(void* const* d_in, const int* in_sizes, int n_in,
                              void* d_out, int out_size)
{
    const float* feat     = (const float*)d_in[0];
    const int*   edge_dst = (const int*)d_in[2];
    float*       out      = (float*)d_out;

    const int B   = out_size / D_DIM;   // 50000
    const int E   = in_sizes[2];        // 850000
    const int epn = E / B;              // 17

    const int threads = 256;            // 8 warps/block
    const int blocks  = (B * 32 + threads - 1) / threads;

    if (epn == 17) {
        mean_agg_kernel_fixed<17><<<blocks, threads>>>(feat, edge_dst, out, B);
    } else {
        mean_agg_kernel_dyn<<<blocks, threads>>>(feat, edge_dst, out, B, epn);
    }
}